// round 14
// baseline (speedup 1.0000x reference)
#include <cuda_runtime.h>
#include <cstdint>

#define TT 256
#define HH 512
#define VV 32
#define NBATCH 16
#define THREADS 512

typedef unsigned long long u64;

// ---------------- device scratch (static, no allocation) ----------------
__device__ float g_Kproj[NBATCH*TT*HH];     // 8 MB
__device__ float g_q[NBATCH*HH];
__device__ float g_scores[NBATCH*TT];
__device__ float g_ctx[NBATCH*HH];
__device__ float g_h0[2][NBATCH*HH];
__device__ float g_c0[2][NBATCH*HH];
__device__ float g_h1[2][NBATCH*HH];
__device__ float g_c1[2][NBATCH*HH];

// barrier state: monotonic across launches (graph replays) -> no reset race
__device__ unsigned g_epoch;
__device__ unsigned g_arrive;
__device__ unsigned g_release;

// ---------------- smem layout (floats) ----------------
// [0, 24576)        phase staging (A/B/D/E share; D peak 24576)
// [24576, 25360)    phase C buffers (ws 256 | red 16 | sP 512)
// [25360, 25872)    vs: v vector, staged once
#define CWS   24576
#define CRED  24832
#define CSP   24848
#define VSOFF 25360
#define SMEM_BYTES (25872 * 4)

// ---------------- helpers ----------------
union F4 { float4 v; u64 u[2]; };
union F2 { u64 u; float2 f; };

__device__ __forceinline__ void fma2(u64 &acc, u64 a, u64 b){
    asm("fma.rn.f32x2 %0, %1, %2, %0;" : "+l"(acc) : "l"(a), "l"(b));
}
__device__ __forceinline__ float wsum(float v){
#pragma unroll
    for (int o = 16; o; o >>= 1) v += __shfl_xor_sync(0xffffffffu, v, o);
    return v;
}
__device__ __forceinline__ float wmax(float v){
#pragma unroll
    for (int o = 16; o; o >>= 1) v = fmaxf(v, __shfl_xor_sync(0xffffffffu, v, o));
    return v;
}
__device__ __forceinline__ float sigf(float x){ return 1.0f/(1.0f + __expf(-x)); }

// MUFU-free tanh, |err| ~1e-5
__device__ __forceinline__ float tanh_fast(float x){
    float u = x * 2.8853900817779268f;
    u = fminf(fmaxf(u, -30.0f), 30.0f);
    float big = u + 12582912.0f;
    int e = __float_as_int(big) - 0x4B400000;
    float fn = big - 12582912.0f;
    float f = u - fn;
    float p = 1.3333558e-3f;
    p = fmaf(p, f, 9.6181291e-3f);
    p = fmaf(p, f, 5.5504109e-2f);
    p = fmaf(p, f, 2.4022651e-1f);
    p = fmaf(p, f, 6.9314718e-1f);
    p = fmaf(p, f, 1.0f);
    float t = __int_as_float(__float_as_int(p) + (e << 23));
    float num = t - 1.0f;
    float den = t + 1.0f;
    float r = __uint_as_float(0x7EF311C3u - __float_as_uint(den));
    r = r * fmaf(-den, r, 2.0f);
    r = r * fmaf(-den, r, 2.0f);
    return num * r;
}

// FENCE-FREE grid barrier (R12-proven: no CCTL.IVALL, acq_rel ordering).
// Contract: all cross-block MUTABLE loads are __ldcg; same-warp state is
// own-SM L1 coherent; immutable inputs cache freely in L1.
__device__ __forceinline__ void gridbar(unsigned &ep, int NB){
    __syncthreads();
    ep++;
    if (threadIdx.x == 0){
        unsigned prev;
        asm volatile("atom.add.acq_rel.gpu.u32 %0, [%1], %2;"
                     : "=r"(prev) : "l"(&g_arrive), "r"(1u) : "memory");
        if (prev + 1u == ep * (unsigned)NB){
            asm volatile("st.release.gpu.u32 [%0], %1;"
                         :: "l"(&g_release), "r"(ep) : "memory");
        } else {
            unsigned r;
            do {
                __nanosleep(20);
                asm volatile("ld.acquire.gpu.u32 %0, [%1];"
                             : "=r"(r) : "l"(&g_release) : "memory");
            } while ((int)(r - ep) < 0);
        }
    }
    __syncthreads();
}

// ---------------- batch-shared GEMV row (16 batches, W prefetched) ----------
__device__ __forceinline__ void dotrow16(const float* __restrict__ Wrow,
                                         const float4* __restrict__ hs4,
                                         float bias, float* dst, int dstStride, int lane){
    u64 acc2[16];
#pragma unroll
    for (int b=0;b<16;b++) acc2[b]=0ull;
    const float4* W4 = (const float4*)Wrow;
    F4 Wv[4];
#pragma unroll
    for (int i=0;i<4;i++) Wv[i].v = __ldcg(W4 + lane + 32*i);
#pragma unroll
    for (int i=0;i<4;i++){
#pragma unroll
        for (int b=0;b<16;b++){
            F4 X; X.v = hs4[b*128 + lane + 32*i];
            fma2(acc2[b], Wv[i].u[0], X.u[0]);
            fma2(acc2[b], Wv[i].u[1], X.u[1]);
        }
    }
#pragma unroll
    for (int b=0;b<16;b++){
        F2 z; z.u = acc2[b];
        float s = z.f.x + z.f.y;
        s = wsum(s);
        if (lane==b) dst[(size_t)b*dstStride] = s + bias;
    }
}

// ---------------- LSTM gate accumulation: 4 gates x 4 batches (batch-quarter) ----
template<int K>
__device__ __forceinline__ void accum_quarter(u64 acc[4][4], const float* __restrict__ W,
                                              int row, const float4* __restrict__ xb, int lane){
    constexpr int K4 = K/4;
    const float4* w0 = (const float4*)(W + (size_t)row*K);
    const float4* w1 = (const float4*)(W + (size_t)(row+512)*K);
    const float4* w2 = (const float4*)(W + (size_t)(row+1024)*K);
    const float4* w3 = (const float4*)(W + (size_t)(row+1536)*K);
#pragma unroll
    for (int g = 0; g < K4/64; g++){
        F4 Wb[2][4];
#pragma unroll
        for (int it = 0; it < 2; it++){
            int c = lane + 32*(g*2+it);
            Wb[it][0].v = __ldcg(w0 + c);
            Wb[it][1].v = __ldcg(w1 + c);
            Wb[it][2].v = __ldcg(w2 + c);
            Wb[it][3].v = __ldcg(w3 + c);
        }
#pragma unroll
        for (int it = 0; it < 2; it++){
            int c = lane + 32*(g*2+it);
#pragma unroll
            for (int b = 0; b < 4; b++){
                F4 X; X.v = xb[b*K4 + c];
                fma2(acc[0][b], Wb[it][0].u[0], X.u[0]); fma2(acc[0][b], Wb[it][0].u[1], X.u[1]);
                fma2(acc[1][b], Wb[it][1].u[0], X.u[0]); fma2(acc[1][b], Wb[it][1].u[1], X.u[1]);
                fma2(acc[2][b], Wb[it][2].u[0], X.u[0]); fma2(acc[2][b], Wb[it][2].u[1], X.u[1]);
                fma2(acc[3][b], Wb[it][3].u[0], X.u[0]); fma2(acc[3][b], Wb[it][3].u[1], X.u[1]);
            }
        }
    }
}

__device__ __forceinline__ void finish_quarter(u64 acc[4][4], int cell, int bq,
        const float* __restrict__ bih, const float* __restrict__ bhh,
        const float* __restrict__ cprev, float* __restrict__ hout, float* __restrict__ cout_,
        int lane){
    float keep[4] = {0.f,0.f,0.f,0.f};
#pragma unroll
    for (int b=0;b<4;b++){
#pragma unroll
        for (int g=0; g<4; g++){
            F2 z; z.u = acc[g][b];
            float s = wsum(z.f.x + z.f.y);
            if (lane == b) keep[g] = s;
        }
    }
    if (lane < 4){
        int b = bq*4 + lane, idx = b*HH + cell;
        float gi = keep[0] + bih[cell       ] + bhh[cell       ];
        float gf = keep[1] + bih[cell +  512] + bhh[cell +  512];
        float gg = keep[2] + bih[cell + 1024] + bhh[cell + 1024];
        float go = keep[3] + bih[cell + 1536] + bhh[cell + 1536];
        float cc = sigf(gf)*cprev[idx] + sigf(gi)*tanh_fast(gg);
        cout_[idx] = cc;
        hout [idx] = sigf(go)*tanh_fast(cc);
    }
}

// ---------------- Kproj = enc @ Wk^T + bk (one-time tiled GEMM; first 256 threads) ----
__device__ void kproj_phase(const float* __restrict__ A, const float* __restrict__ W,
                            const float* __restrict__ bias, float* __restrict__ C,
                            float* sm, int NB, int bx, int tid){
    float* As = sm;
    float* Ws = sm + 16*65;
    int lr = tid >> 2;
    int lk = (tid & 3) << 2;
    int tx = tid & 15, ty = (tid >> 4) & 15;
    const bool act = (tid < 256);
    for (int tile = bx; tile < 64*8; tile += NB){
        int m0 = (tile >> 3)*64, n0 = (tile & 7)*64;
        float acc[4][4];
#pragma unroll
        for (int i=0;i<4;i++)
#pragma unroll
            for (int j=0;j<4;j++) acc[i][j]=0.f;
        for (int k0 = 0; k0 < HH; k0 += 16){
            float4 a4 = make_float4(0,0,0,0), w4 = make_float4(0,0,0,0);
            if (act){
                a4 = *(const float4*)(A + (size_t)(m0+lr)*HH + k0 + lk);
                w4 = *(const float4*)(W + (size_t)(n0+lr)*HH + k0 + lk);
            }
            __syncthreads();
            if (act){
                As[(lk+0)*65+lr]=a4.x; As[(lk+1)*65+lr]=a4.y; As[(lk+2)*65+lr]=a4.z; As[(lk+3)*65+lr]=a4.w;
                Ws[(lk+0)*65+lr]=w4.x; Ws[(lk+1)*65+lr]=w4.y; Ws[(lk+2)*65+lr]=w4.z; Ws[(lk+3)*65+lr]=w4.w;
            }
            __syncthreads();
            if (act){
#pragma unroll
                for (int kk=0; kk<16; kk++){
                    float av[4], wv[4];
#pragma unroll
                    for (int i=0;i<4;i++){ av[i]=As[kk*65 + ty*4+i]; wv[i]=Ws[kk*65 + tx*4+i]; }
#pragma unroll
                    for (int i=0;i<4;i++)
#pragma unroll
                        for (int j=0;j<4;j++) acc[i][j] += av[i]*wv[j];
                }
            }
        }
        if (act){
#pragma unroll
            for (int i=0;i<4;i++){
                int m = m0 + ty*4 + i;
#pragma unroll
                for (int j=0;j<4;j++){
                    int n = n0 + tx*4 + j;
                    C[(size_t)m*HH + n] = acc[i][j] + bias[n];
                }
            }
        }
        __syncthreads();
    }
}

// ---------------- the persistent kernel ----------------
__global__ __launch_bounds__(THREADS, 1)
void decoder_persistent(const float* __restrict__ enc, const float* __restrict__ h0in,
                        const float* __restrict__ c0in,
                        const float* __restrict__ Wq, const float* __restrict__ bq,
                        const float* __restrict__ Wk, const float* __restrict__ bk,
                        const float* __restrict__ v,
                        const float* __restrict__ Wih0, const float* __restrict__ bih0,
                        const float* __restrict__ Whh0, const float* __restrict__ bhh0,
                        const float* __restrict__ Wih1, const float* __restrict__ bih1,
                        const float* __restrict__ Whh1, const float* __restrict__ bhh1,
                        const float* __restrict__ Wout, const float* __restrict__ bout,
                        float* __restrict__ out)
{
    extern __shared__ float sm[];
    const int tid = threadIdx.x, bx = blockIdx.x, NB = gridDim.x;
    const int lane = tid & 31, w = tid >> 5;            // 16 warps/block
    const int NW = NB * 16;
    const int wid0 = w*NB + bx;                          // block-strided warp id
    unsigned ep = g_epoch;

    // ---- init + Kproj ----
    for (int i = bx*THREADS + tid; i < NBATCH*HH; i += NB*THREADS){
        g_h0[0][i] = h0in[i];
        g_h1[0][i] = h0in[NBATCH*HH + i];
        g_c0[0][i] = c0in[i];
        g_c1[0][i] = c0in[NBATCH*HH + i];
    }
    kproj_phase(enc, Wk, bk, g_Kproj, sm, NB, bx, tid);
    // stage v once (immutable, persistent high region)
    for (int i = tid; i < HH; i += THREADS) sm[VSOFF + i] = v[i];
    gridbar(ep, NB);

    for (int t = 0; t < TT; t++){
        const int p = t & 1, np = p ^ 1;

        // ---- phase A: q = h1@Wq^T + bq ; logits[t-1] = h1@Wout^T + bout ----
        {
            float4* hs4 = (float4*)sm;
            const float4* hsrc = (const float4*)g_h1[p];
            for (int i = tid; i < 2048; i += THREADS) hs4[i] = __ldcg(hsrc + i);
            __syncthreads();
            for (int task = wid0; task < 544; task += NW){
                if (task < 512)
                    dotrow16(Wq + (size_t)task*HH, hs4, bq[task], g_q + task, HH, lane);
                else if (t > 0){
                    int r = task - 512;
                    dotrow16(Wout + (size_t)r*HH, hs4, bout[r],
                             out + (size_t)(t-1)*VV + r, TT*VV, lane);
                }
            }
        }
        gridbar(ep, NB);

        // ---- phase B: scores[b,tau] = sum_h v[h]*tanh(q[b,h]+Kproj[b,tau,h]) ----
        {
            float4* qs4 = (float4*)sm;
            const float4* qsrc = (const float4*)g_q;
            for (int i = tid; i < 2048; i += THREADS) qs4[i] = __ldcg(qsrc + i);
            __syncthreads();
            const float4* vs4 = (const float4*)(sm + VSOFF);
            for (int pr = wid0; pr < 2048; pr += NW){
                int b = pr >> 7;
                const float4* Ka = (const float4*)(g_Kproj + ((size_t)pr*2)*HH);
                const float4* Kb = Ka + 128;
                float4 ka[4], kb[4];
#pragma unroll
                for (int i = 0; i < 4; i++){
                    ka[i] = __ldcg(Ka + lane + 32*i);
                    kb[i] = __ldcg(Kb + lane + 32*i);
                }
                float a0 = 0.f, a1 = 0.f;
#pragma unroll
                for (int i = 0; i < 4; i++){
                    int c = lane + 32*i;
                    float4 q4 = qs4[b*128 + c];
                    float4 v4 = vs4[c];
                    a0 += v4.x * tanh_fast(q4.x + ka[i].x);
                    a0 += v4.y * tanh_fast(q4.y + ka[i].y);
                    a0 += v4.z * tanh_fast(q4.z + ka[i].z);
                    a0 += v4.w * tanh_fast(q4.w + ka[i].w);
                    a1 += v4.x * tanh_fast(q4.x + kb[i].x);
                    a1 += v4.y * tanh_fast(q4.y + kb[i].y);
                    a1 += v4.z * tanh_fast(q4.z + kb[i].z);
                    a1 += v4.w * tanh_fast(q4.w + kb[i].w);
                }
                a0 = wsum(a0); a1 = wsum(a1);
                if (lane == 0){ g_scores[2*pr] = a0; g_scores[2*pr+1] = a1; }
            }
        }
        gridbar(ep, NB);

        // ---- phase C: softmax + ctx (high-region buffers) ----
        {
            float* ws  = sm + CWS;
            float* red = sm + CRED;
            float* sP  = sm + CSP;
            for (int task = bx; task < 128; task += NB){
                int b = task >> 3, hc = (task & 7) * 64;
                float s = 0.f;
                if (tid < 256){
                    s = __ldcg(&g_scores[b*TT + tid]);
                    float m = wmax(s);
                    if (lane == 0) red[w] = m;
                }
                __syncthreads();
                float mx = red[0];
#pragma unroll
                for (int j = 1; j < 8; j++) mx = fmaxf(mx, red[j]);
                if (tid < 256){
                    float e = __expf(s - mx);
                    ws[tid] = e;
                    float su = wsum(e);
                    if (lane == 0) red[w] = su;
                }
                __syncthreads();
                float tot = red[0];
#pragma unroll
                for (int j = 1; j < 8; j++) tot += red[j];
                float rz = 1.f / tot;
                int h = hc + (tid & 63), stripe = tid >> 6;
                const float* ep_ = enc + ((size_t)(b*TT) + stripe*32)*HH + h;
                float acc = 0.f;
#pragma unroll 8
                for (int tt = 0; tt < 32; tt++) acc += ws[stripe*32 + tt] * __ldcg(ep_ + (size_t)tt*HH);
                sP[tid] = acc; __syncthreads();
                if (tid < 64){
                    float r2 = sP[tid];
#pragma unroll
                    for (int j = 1; j < 8; j++) r2 += sP[tid + 64*j];
                    g_ctx[b*HH + hc + tid] = r2 * rz;
                }
                __syncthreads();
            }
        }
        // ---- PRE-STAGE D (independent of C): enc slice + h0[p] ----
        {
            float4* xs4 = (float4*)sm;                    // [16][256] f4
            float4* hs4 = (float4*)sm + 4096;             // [16][128] f4
            const float4* enc4 = (const float4*)enc;
            for (int i = tid; i < 2048; i += THREADS){
                int b = i >> 7, r = i & 127;
                xs4[b*256 + r] = __ldcg(enc4 + (size_t)(b*TT + t)*128 + r);
            }
            const float4* hsrc = (const float4*)g_h0[p];  // stable since step t-1
            for (int i = tid; i < 2048; i += THREADS) hs4[i] = __ldcg(hsrc + i);
        }
        gridbar(ep, NB);

        // ---- phase D: finish staging (ctx) + LSTM layer 0; 2048 tasks ----
        {
            float4* xs4 = (float4*)sm;
            float4* hs4 = (float4*)sm + 4096;
            const float4* ctx4 = (const float4*)g_ctx;
            for (int i = tid; i < 2048; i += THREADS){
                int b = i >> 7, r = i & 127;
                xs4[b*256 + 128 + r] = __ldcg(ctx4 + b*128 + r);
            }
            __syncthreads();
            for (int task = wid0; task < 2048; task += NW){
                int cell = task >> 2, bq2 = task & 3;
                u64 acc[4][4];
#pragma unroll
                for (int g=0; g<4; g++)
#pragma unroll
                    for (int b=0; b<4; b++) acc[g][b] = 0ull;
                accum_quarter<1024>(acc, Wih0, cell, xs4 + bq2*4*256, lane);
                accum_quarter<512 >(acc, Whh0, cell, (const float4*)hs4 + bq2*4*128, lane);
                finish_quarter(acc, cell, bq2, bih0, bhh0, g_c0[p], g_h0[np], g_c0[np], lane);
            }
        }
        // ---- PRE-STAGE E (independent of D): h1[p] ----
        __syncthreads();                                  // all warps done reading xs4
        {
            float4* ehs4 = (float4*)sm + 2048;            // floats [8192,16384)
            const float4* hsrc = (const float4*)g_h1[p];  // stable since step t-1
            for (int i = tid; i < 2048; i += THREADS) ehs4[i] = __ldcg(hsrc + i);
        }
        gridbar(ep, NB);

        // ---- phase E: finish staging (h0[np]) + LSTM layer 1; 2048 tasks ----
        {
            float4* xs4 = (float4*)sm;                    // [16][128] f4
            float4* hs4 = (float4*)sm + 2048;
            const float4* xsrc = (const float4*)g_h0[np];
            for (int i = tid; i < 2048; i += THREADS) xs4[i] = __ldcg(xsrc + i);
            __syncthreads();
            for (int task = wid0; task < 2048; task += NW){
                int cell = task >> 2, bq2 = task & 3;
                u64 acc[4][4];
#pragma unroll
                for (int g=0; g<4; g++)
#pragma unroll
                    for (int b=0; b<4; b++) acc[g][b] = 0ull;
                accum_quarter<512>(acc, Wih1, cell, xs4 + bq2*4*128, lane);
                accum_quarter<512>(acc, Whh1, cell, (const float4*)hs4 + bq2*4*128, lane);
                finish_quarter(acc, cell, bq2, bih1, bhh1, g_c1[p], g_h1[np], g_c1[np], lane);
            }
        }
        gridbar(ep, NB);
    }

    // ---- final logits for t = 255 (state parity 0 after step 255) ----
    {
        float4* hs4 = (float4*)sm;
        const float4* hsrc = (const float4*)g_h1[0];
        for (int i = tid; i < 2048; i += THREADS) hs4[i] = __ldcg(hsrc + i);
        __syncthreads();
        for (int task = wid0; task < 544; task += NW){
            if (task >= 512){
                int r = task - 512;
                dotrow16(Wout + (size_t)r*HH, hs4, bout[r],
                         out + (size_t)(TT-1)*VV + r, TT*VV, lane);
            }
        }
    }

    if (bx == 0 && tid == 0) g_epoch = ep;   // persist epoch base for next launch
}

// ---------------- launch ----------------
extern "C" void kernel_launch(void* const* d_in, const int* in_sizes, int n_in,
                              void* d_out, int out_size){
    const float* enc   = (const float*)d_in[0];
    const float* h0in  = (const float*)d_in[1];
    const float* c0in  = (const float*)d_in[2];
    // d_in[3] = audio_lengths (unused by the reference math)
    const float* Wq    = (const float*)d_in[4];
    const float* bq    = (const float*)d_in[5];
    const float* Wk    = (const float*)d_in[6];
    const float* bk    = (const float*)d_in[7];
    const float* v     = (const float*)d_in[8];
    // d_in[9] = vb (shift-invariant under softmax; omitted)
    const float* Wih0  = (const float*)d_in[10];
    const float* bih0  = (const float*)d_in[11];
    const float* Whh0  = (const float*)d_in[12];
    const float* bhh0  = (const float*)d_in[13];
    const float* Wih1  = (const float*)d_in[14];
    const float* bih1  = (const float*)d_in[15];
    const float* Whh1  = (const float*)d_in[16];
    const float* bhh1  = (const float*)d_in[17];
    const float* Wout  = (const float*)d_in[18];
    const float* bout  = (const float*)d_in[19];
    float* out = (float*)d_out;

    cudaFuncSetAttribute(decoder_persistent, cudaFuncAttributeMaxDynamicSharedMemorySize, SMEM_BYTES);

    // grid = exactly the number of co-resident blocks (deadlock-proof)
    int dev = 0; cudaGetDevice(&dev);
    int nsm = 0; cudaDeviceGetAttribute(&nsm, cudaDevAttrMultiProcessorCount, dev);
    int maxb = 0;
    cudaOccupancyMaxActiveBlocksPerMultiprocessor(&maxb, decoder_persistent, THREADS, SMEM_BYTES);
    if (maxb < 1) maxb = 1;
    int grid = nsm * maxb;
    if (grid < 1) grid = 1;
    if (grid > 512) grid = 512;

    decoder_persistent<<<grid, THREADS, SMEM_BYTES>>>(enc, h0in, c0in, Wq, bq, Wk, bk, v,
                                                      Wih0, bih0, Whh0, bhh0,
                                                      Wih1, bih1, Whh1, bhh1,
                                                      Wout, bout, out);
}

// round 15
// speedup vs baseline: 1.0418x; 1.0418x over previous
#include <cuda_runtime.h>
#include <cstdint>

#define TT 256
#define HH 512
#define VV 32
#define NBATCH 16
#define THREADS 512

typedef unsigned long long u64;

// ---------------- device scratch (static, no allocation) ----------------
__device__ float g_Kproj[NBATCH*TT*HH];     // 8 MB
__device__ float g_q[NBATCH*HH];
__device__ float g_scores[NBATCH*TT];
__device__ float g_ctx[NBATCH*HH];
__device__ float g_h0[2][NBATCH*HH];
__device__ float g_c0[2][NBATCH*HH];
__device__ float g_h1[2][NBATCH*HH];
__device__ float g_c1[2][NBATCH*HH];

// barrier state: monotonic across launches (graph replays) -> no reset race
__device__ unsigned g_epoch;
__device__ unsigned g_arrive;
__device__ unsigned g_release;

// ---------------- helpers ----------------
union F4 { float4 v; u64 u[2]; };
union F2 { u64 u; float2 f; };

__device__ __forceinline__ void fma2(u64 &acc, u64 a, u64 b){
    asm("fma.rn.f32x2 %0, %1, %2, %0;" : "+l"(acc) : "l"(a), "l"(b));
}
__device__ __forceinline__ float wsum(float v){
#pragma unroll
    for (int o = 16; o; o >>= 1) v += __shfl_xor_sync(0xffffffffu, v, o);
    return v;
}
__device__ __forceinline__ float wmax(float v){
#pragma unroll
    for (int o = 16; o; o >>= 1) v = fmaxf(v, __shfl_xor_sync(0xffffffffu, v, o));
    return v;
}
__device__ __forceinline__ float sigf(float x){ return 1.0f/(1.0f + __expf(-x)); }

// MUFU-free tanh, |err| ~1e-5
__device__ __forceinline__ float tanh_fast(float x){
    float u = x * 2.8853900817779268f;
    u = fminf(fmaxf(u, -30.0f), 30.0f);
    float big = u + 12582912.0f;
    int e = __float_as_int(big) - 0x4B400000;
    float fn = big - 12582912.0f;
    float f = u - fn;
    float p = 1.3333558e-3f;
    p = fmaf(p, f, 9.6181291e-3f);
    p = fmaf(p, f, 5.5504109e-2f);
    p = fmaf(p, f, 2.4022651e-1f);
    p = fmaf(p, f, 6.9314718e-1f);
    p = fmaf(p, f, 1.0f);
    float t = __int_as_float(__float_as_int(p) + (e << 23));
    float num = t - 1.0f;
    float den = t + 1.0f;
    float r = __uint_as_float(0x7EF311C3u - __float_as_uint(den));
    r = r * fmaf(-den, r, 2.0f);
    r = r * fmaf(-den, r, 2.0f);
    return num * r;
}

// FENCE-FREE grid barrier (R12-proven: no CCTL.IVALL, acq_rel ordering).
// Contract: all cross-block MUTABLE loads are __ldcg; same-warp state is
// own-SM L1 coherent; immutable inputs cache freely in L1.
__device__ __forceinline__ void gridbar(unsigned &ep, int NB){
    __syncthreads();
    ep++;
    if (threadIdx.x == 0){
        unsigned prev;
        asm volatile("atom.add.acq_rel.gpu.u32 %0, [%1], %2;"
                     : "=r"(prev) : "l"(&g_arrive), "r"(1u) : "memory");
        if (prev + 1u == ep * (unsigned)NB){
            asm volatile("st.release.gpu.u32 [%0], %1;"
                         :: "l"(&g_release), "r"(ep) : "memory");
        } else {
            unsigned r;
            do {
                asm volatile("ld.acquire.gpu.u32 %0, [%1];"
                             : "=r"(r) : "l"(&g_release) : "memory");
            } while ((int)(r - ep) < 0);
        }
    }
    __syncthreads();
}

// ---------------- batch-shared GEMV row (16 batches, W prefetched) ----------
__device__ __forceinline__ void dotrow16(const float* __restrict__ Wrow,
                                         const float4* __restrict__ hs4,
                                         float bias, float* dst, int dstStride, int lane){
    u64 acc2[16];
#pragma unroll
    for (int b=0;b<16;b++) acc2[b]=0ull;
    const float4* W4 = (const float4*)Wrow;
    F4 Wv[4];
#pragma unroll
    for (int i=0;i<4;i++) Wv[i].v = __ldcg(W4 + lane + 32*i);
#pragma unroll
    for (int i=0;i<4;i++){
#pragma unroll
        for (int b=0;b<16;b++){
            F4 X; X.v = hs4[b*128 + lane + 32*i];
            fma2(acc2[b], Wv[i].u[0], X.u[0]);
            fma2(acc2[b], Wv[i].u[1], X.u[1]);
        }
    }
#pragma unroll
    for (int b=0;b<16;b++){
        F2 z; z.u = acc2[b];
        float s = z.f.x + z.f.y;
        s = wsum(s);
        if (lane==b) dst[(size_t)b*dstStride] = s + bias;
    }
}

// ---------------- LSTM gate accumulation: 4 gates x 4 batches (batch-quarter) ----
template<int K>
__device__ __forceinline__ void accum_quarter(u64 acc[4][4], const float* __restrict__ W,
                                              int row, const float4* __restrict__ xb, int lane){
    constexpr int K4 = K/4;
    const float4* w0 = (const float4*)(W + (size_t)row*K);
    const float4* w1 = (const float4*)(W + (size_t)(row+512)*K);
    const float4* w2 = (const float4*)(W + (size_t)(row+1024)*K);
    const float4* w3 = (const float4*)(W + (size_t)(row+1536)*K);
#pragma unroll
    for (int g = 0; g < K4/64; g++){
        F4 Wb[2][4];
#pragma unroll
        for (int it = 0; it < 2; it++){
            int c = lane + 32*(g*2+it);
            Wb[it][0].v = __ldcg(w0 + c);
            Wb[it][1].v = __ldcg(w1 + c);
            Wb[it][2].v = __ldcg(w2 + c);
            Wb[it][3].v = __ldcg(w3 + c);
        }
#pragma unroll
        for (int it = 0; it < 2; it++){
            int c = lane + 32*(g*2+it);
#pragma unroll
            for (int b = 0; b < 4; b++){
                F4 X; X.v = xb[b*K4 + c];
                fma2(acc[0][b], Wb[it][0].u[0], X.u[0]); fma2(acc[0][b], Wb[it][0].u[1], X.u[1]);
                fma2(acc[1][b], Wb[it][1].u[0], X.u[0]); fma2(acc[1][b], Wb[it][1].u[1], X.u[1]);
                fma2(acc[2][b], Wb[it][2].u[0], X.u[0]); fma2(acc[2][b], Wb[it][2].u[1], X.u[1]);
                fma2(acc[3][b], Wb[it][3].u[0], X.u[0]); fma2(acc[3][b], Wb[it][3].u[1], X.u[1]);
            }
        }
    }
}

__device__ __forceinline__ void finish_quarter(u64 acc[4][4], int cell, int bq,
        const float* __restrict__ bih, const float* __restrict__ bhh,
        const float* __restrict__ cprev, float* __restrict__ hout, float* __restrict__ cout_,
        int lane){
    float keep[4] = {0.f,0.f,0.f,0.f};
#pragma unroll
    for (int b=0;b<4;b++){
#pragma unroll
        for (int g=0; g<4; g++){
            F2 z; z.u = acc[g][b];
            float s = wsum(z.f.x + z.f.y);
            if (lane == b) keep[g] = s;
        }
    }
    if (lane < 4){
        int b = bq*4 + lane, idx = b*HH + cell;
        float gi = keep[0] + bih[cell       ] + bhh[cell       ];
        float gf = keep[1] + bih[cell +  512] + bhh[cell +  512];
        float gg = keep[2] + bih[cell + 1024] + bhh[cell + 1024];
        float go = keep[3] + bih[cell + 1536] + bhh[cell + 1536];
        float cc = sigf(gf)*cprev[idx] + sigf(gi)*tanh_fast(gg);
        cout_[idx] = cc;
        hout [idx] = sigf(go)*tanh_fast(cc);
    }
}

// ---------------- Kproj = enc @ Wk^T + bk (one-time tiled GEMM; first 256 threads) ----
__device__ void kproj_phase(const float* __restrict__ A, const float* __restrict__ W,
                            const float* __restrict__ bias, float* __restrict__ C,
                            float* sm, int NB, int bx, int tid){
    float* As = sm;
    float* Ws = sm + 16*65;
    int lr = tid >> 2;
    int lk = (tid & 3) << 2;
    int tx = tid & 15, ty = (tid >> 4) & 15;
    const bool act = (tid < 256);
    for (int tile = bx; tile < 64*8; tile += NB){
        int m0 = (tile >> 3)*64, n0 = (tile & 7)*64;
        float acc[4][4];
#pragma unroll
        for (int i=0;i<4;i++)
#pragma unroll
            for (int j=0;j<4;j++) acc[i][j]=0.f;
        for (int k0 = 0; k0 < HH; k0 += 16){
            float4 a4 = make_float4(0,0,0,0), w4 = make_float4(0,0,0,0);
            if (act){
                a4 = *(const float4*)(A + (size_t)(m0+lr)*HH + k0 + lk);
                w4 = *(const float4*)(W + (size_t)(n0+lr)*HH + k0 + lk);
            }
            __syncthreads();
            if (act){
                As[(lk+0)*65+lr]=a4.x; As[(lk+1)*65+lr]=a4.y; As[(lk+2)*65+lr]=a4.z; As[(lk+3)*65+lr]=a4.w;
                Ws[(lk+0)*65+lr]=w4.x; Ws[(lk+1)*65+lr]=w4.y; Ws[(lk+2)*65+lr]=w4.z; Ws[(lk+3)*65+lr]=w4.w;
            }
            __syncthreads();
            if (act){
#pragma unroll
                for (int kk=0; kk<16; kk++){
                    float av[4], wv[4];
#pragma unroll
                    for (int i=0;i<4;i++){ av[i]=As[kk*65 + ty*4+i]; wv[i]=Ws[kk*65 + tx*4+i]; }
#pragma unroll
                    for (int i=0;i<4;i++)
#pragma unroll
                        for (int j=0;j<4;j++) acc[i][j] += av[i]*wv[j];
                }
            }
        }
        if (act){
#pragma unroll
            for (int i=0;i<4;i++){
                int m = m0 + ty*4 + i;
#pragma unroll
                for (int j=0;j<4;j++){
                    int n = n0 + tx*4 + j;
                    C[(size_t)m*HH + n] = acc[i][j] + bias[n];
                }
            }
        }
        __syncthreads();
    }
}

// ---------------- the persistent kernel ----------------
__global__ __launch_bounds__(THREADS, 1)
void decoder_persistent(const float* __restrict__ enc, const float* __restrict__ h0in,
                        const float* __restrict__ c0in,
                        const float* __restrict__ Wq, const float* __restrict__ bq,
                        const float* __restrict__ Wk, const float* __restrict__ bk,
                        const float* __restrict__ v,
                        const float* __restrict__ Wih0, const float* __restrict__ bih0,
                        const float* __restrict__ Whh0, const float* __restrict__ bhh0,
                        const float* __restrict__ Wih1, const float* __restrict__ bih1,
                        const float* __restrict__ Whh1, const float* __restrict__ bhh1,
                        const float* __restrict__ Wout, const float* __restrict__ bout,
                        float* __restrict__ out)
{
    extern __shared__ float sm[];
    const int tid = threadIdx.x, bx = blockIdx.x, NB = gridDim.x;
    const int lane = tid & 31, w = tid >> 5;            // 16 warps/block
    const int NW = NB * 16;
    const int wid0 = w*NB + bx;                          // block-strided warp id
    unsigned ep = g_epoch;

    // ---- init + Kproj ----
    for (int i = bx*THREADS + tid; i < NBATCH*HH; i += NB*THREADS){
        g_h0[0][i] = h0in[i];
        g_h1[0][i] = h0in[NBATCH*HH + i];
        g_c0[0][i] = c0in[i];
        g_c1[0][i] = c0in[NBATCH*HH + i];
    }
    kproj_phase(enc, Wk, bk, g_Kproj, sm, NB, bx, tid);
    gridbar(ep, NB);

    for (int t = 0; t < TT; t++){
        const int p = t & 1, np = p ^ 1;

        // ---- phase A: q = h1@Wq^T + bq ; logits[t-1] = h1@Wout^T + bout ----
        {
            float4* hs4 = (float4*)sm;
            const float4* hsrc = (const float4*)g_h1[p];
            for (int i = tid; i < 2048; i += THREADS) hs4[i] = __ldcg(hsrc + i);
            __syncthreads();
            for (int task = wid0; task < 544; task += NW){
                if (task < 512)
                    dotrow16(Wq + (size_t)task*HH, hs4, bq[task], g_q + task, HH, lane);
                else if (t > 0){
                    int r = task - 512;
                    dotrow16(Wout + (size_t)r*HH, hs4, bout[r],
                             out + (size_t)(t-1)*VV + r, TT*VV, lane);
                }
            }
        }
        gridbar(ep, NB);

        // ---- phase B: scores[b,tau] = sum_h v[h]*tanh(q[b,h]+Kproj[b,tau,h]) ----
        {
            float4* qs4 = (float4*)sm;
            float*  vs  = sm + NBATCH*HH;
            const float4* qsrc = (const float4*)g_q;
            for (int i = tid; i < 2048; i += THREADS) qs4[i] = __ldcg(qsrc + i);
            for (int i = tid; i < HH;  i += THREADS) vs[i] = v[i];
            __syncthreads();
            const float4* vs4 = (const float4*)vs;
            for (int pr = wid0; pr < 2048; pr += NW){
                int b = pr >> 7;
                const float4* Ka = (const float4*)(g_Kproj + ((size_t)pr*2)*HH);
                const float4* Kb = Ka + 128;
                float4 ka[4], kb[4];
#pragma unroll
                for (int i = 0; i < 4; i++){
                    ka[i] = __ldcg(Ka + lane + 32*i);
                    kb[i] = __ldcg(Kb + lane + 32*i);
                }
                float a0 = 0.f, a1 = 0.f;
#pragma unroll
                for (int i = 0; i < 4; i++){
                    int c = lane + 32*i;
                    float4 q4 = qs4[b*128 + c];
                    float4 v4 = vs4[c];
                    a0 += v4.x * tanh_fast(q4.x + ka[i].x);
                    a0 += v4.y * tanh_fast(q4.y + ka[i].y);
                    a0 += v4.z * tanh_fast(q4.z + ka[i].z);
                    a0 += v4.w * tanh_fast(q4.w + ka[i].w);
                    a1 += v4.x * tanh_fast(q4.x + kb[i].x);
                    a1 += v4.y * tanh_fast(q4.y + kb[i].y);
                    a1 += v4.z * tanh_fast(q4.z + kb[i].z);
                    a1 += v4.w * tanh_fast(q4.w + kb[i].w);
                }
                a0 = wsum(a0); a1 = wsum(a1);
                if (lane == 0){ g_scores[2*pr] = a0; g_scores[2*pr+1] = a1; }
            }
        }
        gridbar(ep, NB);

        // ---- phase C: softmax over T + ctx = w @ enc (128 tasks: 16b x 8 h-chunks) ----
        {
            float* ws  = sm;          // [256]
            float* red = sm + 256;    // [8]
            float* sP  = sm + 272;    // [512]
            for (int task = bx; task < 128; task += NB){
                int b = task >> 3, hc = (task & 7) * 64;
                float s = 0.f;
                if (tid < 256){
                    s = __ldcg(&g_scores[b*TT + tid]);   // mutable cross-block: L2
                    float m = wmax(s);
                    if (lane == 0) red[w] = m;
                }
                __syncthreads();
                float mx = red[0];
#pragma unroll
                for (int j = 1; j < 8; j++) mx = fmaxf(mx, red[j]);
                if (tid < 256){
                    float e = __expf(s - mx);
                    ws[tid] = e;
                    float su = wsum(e);
                    if (lane == 0) red[w] = su;
                }
                __syncthreads();
                float tot = red[0];
#pragma unroll
                for (int j = 1; j < 8; j++) tot += red[j];
                float rz = 1.f / tot;
                int h = hc + (tid & 63), stripe = tid >> 6;       // 8 stripes of 32 taus
                const float* ep_ = enc + ((size_t)(b*TT) + stripe*32)*HH + h;
                float acc = 0.f;
#pragma unroll 8
                for (int tt = 0; tt < 32; tt++) acc += ws[stripe*32 + tt] * __ldcg(ep_ + (size_t)tt*HH);
                sP[tid] = acc; __syncthreads();
                if (tid < 64){
                    float r2 = sP[tid];
#pragma unroll
                    for (int j = 1; j < 8; j++) r2 += sP[tid + 64*j];
                    g_ctx[b*HH + hc + tid] = r2 * rz;
                }
                __syncthreads();
            }
        }
        gridbar(ep, NB);

        // ---- phase D: LSTM layer 0, K=1536 total; 2048 tasks (cell, bquarter) ----
        {
            float4* xs4 = (float4*)sm;                    // [16][256] float4 = 64KB
            float4* hs4 = (float4*)(sm + NBATCH*1024);    // [16][128] float4 = 32KB
            const float4* enc4 = (const float4*)enc;
            const float4* ctx4 = (const float4*)g_ctx;
            for (int i = tid; i < 4096; i += THREADS){
                int b = i >> 8, r = i & 255;
                xs4[i] = (r < 128) ? __ldcg(enc4 + (size_t)(b*TT + t)*128 + r)
                                   : __ldcg(ctx4 + b*128 + (r - 128));
            }
            const float4* hsrc = (const float4*)g_h0[p];
            for (int i = tid; i < 2048; i += THREADS) hs4[i] = __ldcg(hsrc + i);
            __syncthreads();
            for (int task = wid0; task < 2048; task += NW){
                int cell = task >> 2, bq2 = task & 3;
                u64 acc[4][4];
#pragma unroll
                for (int g=0; g<4; g++)
#pragma unroll
                    for (int b=0; b<4; b++) acc[g][b] = 0ull;
                accum_quarter<1024>(acc, Wih0, cell, xs4 + bq2*4*256, lane);
                accum_quarter<512 >(acc, Whh0, cell, hs4 + bq2*4*128, lane);
                finish_quarter(acc, cell, bq2, bih0, bhh0, g_c0[p], g_h0[np], g_c0[np], lane);
            }
        }
        gridbar(ep, NB);

        // ---- phase E: LSTM layer 1, K=1024 total; 2048 tasks ----
        {
            float4* xs4 = (float4*)sm;                    // [16][128] float4
            float4* hs4 = (float4*)(sm + NBATCH*HH);      // [16][128] float4
            const float4* xsrc = (const float4*)g_h0[np];
            const float4* hsrc = (const float4*)g_h1[p];
            for (int i = tid; i < 2048; i += THREADS){
                xs4[i] = __ldcg(xsrc + i);
                hs4[i] = __ldcg(hsrc + i);
            }
            __syncthreads();
            for (int task = wid0; task < 2048; task += NW){
                int cell = task >> 2, bq2 = task & 3;
                u64 acc[4][4];
#pragma unroll
                for (int g=0; g<4; g++)
#pragma unroll
                    for (int b=0; b<4; b++) acc[g][b] = 0ull;
                accum_quarter<512>(acc, Wih1, cell, xs4 + bq2*4*128, lane);
                accum_quarter<512>(acc, Whh1, cell, hs4 + bq2*4*128, lane);
                finish_quarter(acc, cell, bq2, bih1, bhh1, g_c1[p], g_h1[np], g_c1[np], lane);
            }
        }
        gridbar(ep, NB);
    }

    // ---- final logits for t = 255 (state parity 0 after step 255) ----
    {
        float4* hs4 = (float4*)sm;
        const float4* hsrc = (const float4*)g_h1[0];
        for (int i = tid; i < 2048; i += THREADS) hs4[i] = __ldcg(hsrc + i);
        __syncthreads();
        for (int task = wid0; task < 544; task += NW){
            if (task >= 512){
                int r = task - 512;
                dotrow16(Wout + (size_t)r*HH, hs4, bout[r],
                         out + (size_t)(TT-1)*VV + r, TT*VV, lane);
            }
        }
    }

    if (bx == 0 && tid == 0) g_epoch = ep;   // persist epoch base for next launch
}

// ---------------- launch ----------------
extern "C" void kernel_launch(void* const* d_in, const int* in_sizes, int n_in,
                              void* d_out, int out_size){
    const float* enc   = (const float*)d_in[0];
    const float* h0in  = (const float*)d_in[1];
    const float* c0in  = (const float*)d_in[2];
    // d_in[3] = audio_lengths (unused by the reference math)
    const float* Wq    = (const float*)d_in[4];
    const float* bq    = (const float*)d_in[5];
    const float* Wk    = (const float*)d_in[6];
    const float* bk    = (const float*)d_in[7];
    const float* v     = (const float*)d_in[8];
    // d_in[9] = vb (shift-invariant under softmax; omitted)
    const float* Wih0  = (const float*)d_in[10];
    const float* bih0  = (const float*)d_in[11];
    const float* Whh0  = (const float*)d_in[12];
    const float* bhh0  = (const float*)d_in[13];
    const float* Wih1  = (const float*)d_in[14];
    const float* bih1  = (const float*)d_in[15];
    const float* Whh1  = (const float*)d_in[16];
    const float* bhh1  = (const float*)d_in[17];
    const float* Wout  = (const float*)d_in[18];
    const float* bout  = (const float*)d_in[19];
    float* out = (float*)d_out;

    const int SMEM = (NBATCH*1024 + NBATCH*512) * 4;   // 98304 bytes (phase D peak)
    cudaFuncSetAttribute(decoder_persistent, cudaFuncAttributeMaxDynamicSharedMemorySize, SMEM);

    // grid = exactly the number of co-resident blocks (deadlock-proof)
    int dev = 0; cudaGetDevice(&dev);
    int nsm = 0; cudaDeviceGetAttribute(&nsm, cudaDevAttrMultiProcessorCount, dev);
    int maxb = 0;
    cudaOccupancyMaxActiveBlocksPerMultiprocessor(&maxb, decoder_persistent, THREADS, SMEM);
    if (maxb < 1) maxb = 1;
    int grid = nsm * maxb;
    if (grid < 1) grid = 1;
    if (grid > 512) grid = 512;

    decoder_persistent<<<grid, THREADS, SMEM>>>(enc, h0in, c0in, Wq, bq, Wk, bk, v,
                                                Wih0, bih0, Whh0, bhh0,
                                                Wih1, bih1, Whh1, bhh1,
                                                Wout, bout, out);
}

// round 16
// speedup vs baseline: 1.0600x; 1.0175x over previous
#include <cuda_runtime.h>
#include <cstdint>

#define TT 256
#define HH 512
#define VV 32
#define NBATCH 16
#define THREADS 512

typedef unsigned long long u64;

// ---------------- device scratch (static, no allocation) ----------------
__device__ float g_Kproj[NBATCH*TT*HH];     // 8 MB
__device__ float g_q[NBATCH*HH];
__device__ float g_scores[NBATCH*TT];
__device__ float g_ctx[NBATCH*HH];
__device__ float g_h0[2][NBATCH*HH];
__device__ float g_c0[2][NBATCH*HH];
__device__ float g_h1[2][NBATCH*HH];
__device__ float g_c1[2][NBATCH*HH];

// barrier state: monotonic across launches (graph replays) -> no reset race
__device__ unsigned g_epoch;
__device__ unsigned g_arrive;
__device__ unsigned g_release;

// ---------------- helpers ----------------
union F4 { float4 v; u64 u[2]; };
union F2 { u64 u; float2 f; };

__device__ __forceinline__ void fma2(u64 &acc, u64 a, u64 b){
    asm("fma.rn.f32x2 %0, %1, %2, %0;" : "+l"(acc) : "l"(a), "l"(b));
}
__device__ __forceinline__ float wsum(float v){
#pragma unroll
    for (int o = 16; o; o >>= 1) v += __shfl_xor_sync(0xffffffffu, v, o);
    return v;
}
__device__ __forceinline__ float wmax(float v){
#pragma unroll
    for (int o = 16; o; o >>= 1) v = fmaxf(v, __shfl_xor_sync(0xffffffffu, v, o));
    return v;
}
__device__ __forceinline__ float sigf(float x){ return 1.0f/(1.0f + __expf(-x)); }

// MUFU-free tanh, |err| ~1e-5
__device__ __forceinline__ float tanh_fast(float x){
    float u = x * 2.8853900817779268f;
    u = fminf(fmaxf(u, -30.0f), 30.0f);
    float big = u + 12582912.0f;
    int e = __float_as_int(big) - 0x4B400000;
    float fn = big - 12582912.0f;
    float f = u - fn;
    float p = 1.3333558e-3f;
    p = fmaf(p, f, 9.6181291e-3f);
    p = fmaf(p, f, 5.5504109e-2f);
    p = fmaf(p, f, 2.4022651e-1f);
    p = fmaf(p, f, 6.9314718e-1f);
    p = fmaf(p, f, 1.0f);
    float t = __int_as_float(__float_as_int(p) + (e << 23));
    float num = t - 1.0f;
    float den = t + 1.0f;
    float r = __uint_as_float(0x7EF311C3u - __float_as_uint(den));
    r = r * fmaf(-den, r, 2.0f);
    r = r * fmaf(-den, r, 2.0f);
    return num * r;
}

// FENCE-FREE grid barrier (R12-proven: no CCTL.IVALL, acq_rel ordering).
// Contract: all cross-block MUTABLE loads are __ldcg; same-warp state is
// own-SM L1 coherent; immutable inputs cache freely in L1.
__device__ __forceinline__ void gridbar(unsigned &ep, int NB){
    __syncthreads();
    ep++;
    if (threadIdx.x == 0){
        unsigned prev;
        asm volatile("atom.add.acq_rel.gpu.u32 %0, [%1], %2;"
                     : "=r"(prev) : "l"(&g_arrive), "r"(1u) : "memory");
        if (prev + 1u == ep * (unsigned)NB){
            asm volatile("st.release.gpu.u32 [%0], %1;"
                         :: "l"(&g_release), "r"(ep) : "memory");
        } else {
            unsigned r;
            do {
                asm volatile("ld.acquire.gpu.u32 %0, [%1];"
                             : "=r"(r) : "l"(&g_release) : "memory");
            } while ((int)(r - ep) < 0);
        }
    }
    __syncthreads();
}

// ---------------- batch-shared GEMV row (16 batches, W prefetched) ----------
__device__ __forceinline__ void dotrow16(const float* __restrict__ Wrow,
                                         const float4* __restrict__ hs4,
                                         float bias, float* dst, int dstStride, int lane){
    u64 acc2[16];
#pragma unroll
    for (int b=0;b<16;b++) acc2[b]=0ull;
    const float4* W4 = (const float4*)Wrow;
    F4 Wv[4];
#pragma unroll
    for (int i=0;i<4;i++) Wv[i].v = __ldcg(W4 + lane + 32*i);
#pragma unroll
    for (int i=0;i<4;i++){
#pragma unroll
        for (int b=0;b<16;b++){
            F4 X; X.v = hs4[b*128 + lane + 32*i];
            fma2(acc2[b], Wv[i].u[0], X.u[0]);
            fma2(acc2[b], Wv[i].u[1], X.u[1]);
        }
    }
#pragma unroll
    for (int b=0;b<16;b++){
        F2 z; z.u = acc2[b];
        float s = z.f.x + z.f.y;
        s = wsum(s);
        if (lane==b) dst[(size_t)b*dstStride] = s + bias;
    }
}

// ---------------- LSTM gate accumulation: 4 gates x 4 batches ----
// 16-deep weight prefetch groups (Wb[4][4] = 64 regs): K=1024 -> 2 L2 round
// trips, K=512 -> 1. Halves the per-task dependent-latency chain vs 8-deep.
template<int K>
__device__ __forceinline__ void accum_quarter(u64 acc[4][4], const float* __restrict__ W,
                                              int row, const float4* __restrict__ xb, int lane){
    constexpr int K4 = K/4;
    const float4* w0 = (const float4*)(W + (size_t)row*K);
    const float4* w1 = (const float4*)(W + (size_t)(row+512)*K);
    const float4* w2 = (const float4*)(W + (size_t)(row+1024)*K);
    const float4* w3 = (const float4*)(W + (size_t)(row+1536)*K);
#pragma unroll
    for (int g = 0; g < K4/128; g++){
        F4 Wb[4][4];
#pragma unroll
        for (int it = 0; it < 4; it++){
            int c = lane + 32*(g*4+it);
            Wb[it][0].v = __ldcg(w0 + c);
            Wb[it][1].v = __ldcg(w1 + c);
            Wb[it][2].v = __ldcg(w2 + c);
            Wb[it][3].v = __ldcg(w3 + c);
        }
#pragma unroll
        for (int it = 0; it < 4; it++){
            int c = lane + 32*(g*4+it);
#pragma unroll
            for (int b = 0; b < 4; b++){
                F4 X; X.v = xb[b*K4 + c];
                fma2(acc[0][b], Wb[it][0].u[0], X.u[0]); fma2(acc[0][b], Wb[it][0].u[1], X.u[1]);
                fma2(acc[1][b], Wb[it][1].u[0], X.u[0]); fma2(acc[1][b], Wb[it][1].u[1], X.u[1]);
                fma2(acc[2][b], Wb[it][2].u[0], X.u[0]); fma2(acc[2][b], Wb[it][2].u[1], X.u[1]);
                fma2(acc[3][b], Wb[it][3].u[0], X.u[0]); fma2(acc[3][b], Wb[it][3].u[1], X.u[1]);
            }
        }
    }
}

__device__ __forceinline__ void finish_quarter(u64 acc[4][4], int cell, int bq,
        const float* __restrict__ bih, const float* __restrict__ bhh,
        const float* __restrict__ cprev, float* __restrict__ hout, float* __restrict__ cout_,
        int lane){
    float keep[4] = {0.f,0.f,0.f,0.f};
#pragma unroll
    for (int b=0;b<4;b++){
#pragma unroll
        for (int g=0; g<4; g++){
            F2 z; z.u = acc[g][b];
            float s = wsum(z.f.x + z.f.y);
            if (lane == b) keep[g] = s;
        }
    }
    if (lane < 4){
        int b = bq*4 + lane, idx = b*HH + cell;
        float gi = keep[0] + bih[cell       ] + bhh[cell       ];
        float gf = keep[1] + bih[cell +  512] + bhh[cell +  512];
        float gg = keep[2] + bih[cell + 1024] + bhh[cell + 1024];
        float go = keep[3] + bih[cell + 1536] + bhh[cell + 1536];
        float cc = sigf(gf)*cprev[idx] + sigf(gi)*tanh_fast(gg);
        cout_[idx] = cc;
        hout [idx] = sigf(go)*tanh_fast(cc);
    }
}

// ---------------- Kproj = enc @ Wk^T + bk (one-time tiled GEMM; first 256 threads) ----
__device__ void kproj_phase(const float* __restrict__ A, const float* __restrict__ W,
                            const float* __restrict__ bias, float* __restrict__ C,
                            float* sm, int NB, int bx, int tid){
    float* As = sm;
    float* Ws = sm + 16*65;
    int lr = tid >> 2;
    int lk = (tid & 3) << 2;
    int tx = tid & 15, ty = (tid >> 4) & 15;
    const bool act = (tid < 256);
    for (int tile = bx; tile < 64*8; tile += NB){
        int m0 = (tile >> 3)*64, n0 = (tile & 7)*64;
        float acc[4][4];
#pragma unroll
        for (int i=0;i<4;i++)
#pragma unroll
            for (int j=0;j<4;j++) acc[i][j]=0.f;
        for (int k0 = 0; k0 < HH; k0 += 16){
            float4 a4 = make_float4(0,0,0,0), w4 = make_float4(0,0,0,0);
            if (act){
                a4 = *(const float4*)(A + (size_t)(m0+lr)*HH + k0 + lk);
                w4 = *(const float4*)(W + (size_t)(n0+lr)*HH + k0 + lk);
            }
            __syncthreads();
            if (act){
                As[(lk+0)*65+lr]=a4.x; As[(lk+1)*65+lr]=a4.y; As[(lk+2)*65+lr]=a4.z; As[(lk+3)*65+lr]=a4.w;
                Ws[(lk+0)*65+lr]=w4.x; Ws[(lk+1)*65+lr]=w4.y; Ws[(lk+2)*65+lr]=w4.z; Ws[(lk+3)*65+lr]=w4.w;
            }
            __syncthreads();
            if (act){
#pragma unroll
                for (int kk=0; kk<16; kk++){
                    float av[4], wv[4];
#pragma unroll
                    for (int i=0;i<4;i++){ av[i]=As[kk*65 + ty*4+i]; wv[i]=Ws[kk*65 + tx*4+i]; }
#pragma unroll
                    for (int i=0;i<4;i++)
#pragma unroll
                        for (int j=0;j<4;j++) acc[i][j] += av[i]*wv[j];
                }
            }
        }
        if (act){
#pragma unroll
            for (int i=0;i<4;i++){
                int m = m0 + ty*4 + i;
#pragma unroll
                for (int j=0;j<4;j++){
                    int n = n0 + tx*4 + j;
                    C[(size_t)m*HH + n] = acc[i][j] + bias[n];
                }
            }
        }
        __syncthreads();
    }
}

// ---------------- the persistent kernel ----------------
__global__ __launch_bounds__(THREADS, 1)
void decoder_persistent(const float* __restrict__ enc, const float* __restrict__ h0in,
                        const float* __restrict__ c0in,
                        const float* __restrict__ Wq, const float* __restrict__ bq,
                        const float* __restrict__ Wk, const float* __restrict__ bk,
                        const float* __restrict__ v,
                        const float* __restrict__ Wih0, const float* __restrict__ bih0,
                        const float* __restrict__ Whh0, const float* __restrict__ bhh0,
                        const float* __restrict__ Wih1, const float* __restrict__ bih1,
                        const float* __restrict__ Whh1, const float* __restrict__ bhh1,
                        const float* __restrict__ Wout, const float* __restrict__ bout,
                        float* __restrict__ out)
{
    extern __shared__ float sm[];
    const int tid = threadIdx.x, bx = blockIdx.x, NB = gridDim.x;
    const int lane = tid & 31, w = tid >> 5;            // 16 warps/block
    const int NW = NB * 16;
    const int wid0 = w*NB + bx;                          // block-strided warp id
    unsigned ep = g_epoch;

    // ---- init + Kproj ----
    for (int i = bx*THREADS + tid; i < NBATCH*HH; i += NB*THREADS){
        g_h0[0][i] = h0in[i];
        g_h1[0][i] = h0in[NBATCH*HH + i];
        g_c0[0][i] = c0in[i];
        g_c1[0][i] = c0in[NBATCH*HH + i];
    }
    kproj_phase(enc, Wk, bk, g_Kproj, sm, NB, bx, tid);
    gridbar(ep, NB);

    for (int t = 0; t < TT; t++){
        const int p = t & 1, np = p ^ 1;

        // ---- phase A: q = h1@Wq^T + bq ; logits[t-1] = h1@Wout^T + bout ----
        {
            float4* hs4 = (float4*)sm;
            const float4* hsrc = (const float4*)g_h1[p];
            for (int i = tid; i < 2048; i += THREADS) hs4[i] = __ldcg(hsrc + i);
            __syncthreads();
            for (int task = wid0; task < 544; task += NW){
                if (task < 512)
                    dotrow16(Wq + (size_t)task*HH, hs4, bq[task], g_q + task, HH, lane);
                else if (t > 0){
                    int r = task - 512;
                    dotrow16(Wout + (size_t)r*HH, hs4, bout[r],
                             out + (size_t)(t-1)*VV + r, TT*VV, lane);
                }
            }
        }
        gridbar(ep, NB);

        // ---- phase B: scores[b,tau] = sum_h v[h]*tanh(q[b,h]+Kproj[b,tau,h]) ----
        {
            float4* qs4 = (float4*)sm;
            float*  vs  = sm + NBATCH*HH;
            const float4* qsrc = (const float4*)g_q;
            for (int i = tid; i < 2048; i += THREADS) qs4[i] = __ldcg(qsrc + i);
            for (int i = tid; i < HH;  i += THREADS) vs[i] = v[i];
            __syncthreads();
            const float4* vs4 = (const float4*)vs;
            for (int pr = wid0; pr < 2048; pr += NW){
                int b = pr >> 7;
                const float4* Ka = (const float4*)(g_Kproj + ((size_t)pr*2)*HH);
                const float4* Kb = Ka + 128;
                float4 ka[4], kb[4];
#pragma unroll
                for (int i = 0; i < 4; i++){
                    ka[i] = __ldcg(Ka + lane + 32*i);
                    kb[i] = __ldcg(Kb + lane + 32*i);
                }
                float a0 = 0.f, a1 = 0.f;
#pragma unroll
                for (int i = 0; i < 4; i++){
                    int c = lane + 32*i;
                    float4 q4 = qs4[b*128 + c];
                    float4 v4 = vs4[c];
                    a0 += v4.x * tanh_fast(q4.x + ka[i].x);
                    a0 += v4.y * tanh_fast(q4.y + ka[i].y);
                    a0 += v4.z * tanh_fast(q4.z + ka[i].z);
                    a0 += v4.w * tanh_fast(q4.w + ka[i].w);
                    a1 += v4.x * tanh_fast(q4.x + kb[i].x);
                    a1 += v4.y * tanh_fast(q4.y + kb[i].y);
                    a1 += v4.z * tanh_fast(q4.z + kb[i].z);
                    a1 += v4.w * tanh_fast(q4.w + kb[i].w);
                }
                a0 = wsum(a0); a1 = wsum(a1);
                if (lane == 0){ g_scores[2*pr] = a0; g_scores[2*pr+1] = a1; }
            }
        }
        gridbar(ep, NB);

        // ---- phase C: softmax over T + ctx = w @ enc (128 tasks: 16b x 8 h-chunks) ----
        {
            float* ws  = sm;          // [256]
            float* red = sm + 256;    // [8]
            float* sP  = sm + 272;    // [512]
            for (int task = bx; task < 128; task += NB){
                int b = task >> 3, hc = (task & 7) * 64;
                float s = 0.f;
                if (tid < 256){
                    s = __ldcg(&g_scores[b*TT + tid]);   // mutable cross-block: L2
                    float m = wmax(s);
                    if (lane == 0) red[w] = m;
                }
                __syncthreads();
                float mx = red[0];
#pragma unroll
                for (int j = 1; j < 8; j++) mx = fmaxf(mx, red[j]);
                if (tid < 256){
                    float e = __expf(s - mx);
                    ws[tid] = e;
                    float su = wsum(e);
                    if (lane == 0) red[w] = su;
                }
                __syncthreads();
                float tot = red[0];
#pragma unroll
                for (int j = 1; j < 8; j++) tot += red[j];
                float rz = 1.f / tot;
                int h = hc + (tid & 63), stripe = tid >> 6;       // 8 stripes of 32 taus
                const float* ep_ = enc + ((size_t)(b*TT) + stripe*32)*HH + h;
                // fully unrolled: all 32 column loads in flight -> 1 L2 round trip
                float ld[32];
#pragma unroll
                for (int tt = 0; tt < 32; tt++) ld[tt] = __ldcg(ep_ + (size_t)tt*HH);
                float acc = 0.f;
#pragma unroll
                for (int tt = 0; tt < 32; tt++) acc = fmaf(ws[stripe*32 + tt], ld[tt], acc);
                sP[tid] = acc; __syncthreads();
                if (tid < 64){
                    float r2 = sP[tid];
#pragma unroll
                    for (int j = 1; j < 8; j++) r2 += sP[tid + 64*j];
                    g_ctx[b*HH + hc + tid] = r2 * rz;
                }
                __syncthreads();
            }
        }
        gridbar(ep, NB);

        // ---- phase D: LSTM layer 0, K=1536 total; 2048 tasks (cell, bquarter) ----
        {
            float4* xs4 = (float4*)sm;                    // [16][256] float4 = 64KB
            float4* hs4 = (float4*)(sm + NBATCH*1024);    // [16][128] float4 = 32KB
            const float4* enc4 = (const float4*)enc;
            const float4* ctx4 = (const float4*)g_ctx;
            for (int i = tid; i < 4096; i += THREADS){
                int b = i >> 8, r = i & 255;
                xs4[i] = (r < 128) ? __ldcg(enc4 + (size_t)(b*TT + t)*128 + r)
                                   : __ldcg(ctx4 + b*128 + (r - 128));
            }
            const float4* hsrc = (const float4*)g_h0[p];
            for (int i = tid; i < 2048; i += THREADS) hs4[i] = __ldcg(hsrc + i);
            __syncthreads();
            for (int task = wid0; task < 2048; task += NW){
                int cell = task >> 2, bq2 = task & 3;
                u64 acc[4][4];
#pragma unroll
                for (int g=0; g<4; g++)
#pragma unroll
                    for (int b=0; b<4; b++) acc[g][b] = 0ull;
                accum_quarter<1024>(acc, Wih0, cell, xs4 + bq2*4*256, lane);
                accum_quarter<512 >(acc, Whh0, cell, hs4 + bq2*4*128, lane);
                finish_quarter(acc, cell, bq2, bih0, bhh0, g_c0[p], g_h0[np], g_c0[np], lane);
            }
        }
        gridbar(ep, NB);

        // ---- phase E: LSTM layer 1, K=1024 total; 2048 tasks ----
        {
            float4* xs4 = (float4*)sm;                    // [16][128] float4
            float4* hs4 = (float4*)(sm + NBATCH*HH);      // [16][128] float4
            const float4* xsrc = (const float4*)g_h0[np];
            const float4* hsrc = (const float4*)g_h1[p];
            for (int i = tid; i < 2048; i += THREADS){
                xs4[i] = __ldcg(xsrc + i);
                hs4[i] = __ldcg(hsrc + i);
            }
            __syncthreads();
            for (int task = wid0; task < 2048; task += NW){
                int cell = task >> 2, bq2 = task & 3;
                u64 acc[4][4];
#pragma unroll
                for (int g=0; g<4; g++)
#pragma unroll
                    for (int b=0; b<4; b++) acc[g][b] = 0ull;
                accum_quarter<512>(acc, Wih1, cell, xs4 + bq2*4*128, lane);
                accum_quarter<512>(acc, Whh1, cell, hs4 + bq2*4*128, lane);
                finish_quarter(acc, cell, bq2, bih1, bhh1, g_c1[p], g_h1[np], g_c1[np], lane);
            }
        }
        gridbar(ep, NB);
    }

    // ---- final logits for t = 255 (state parity 0 after step 255) ----
    {
        float4* hs4 = (float4*)sm;
        const float4* hsrc = (const float4*)g_h1[0];
        for (int i = tid; i < 2048; i += THREADS) hs4[i] = __ldcg(hsrc + i);
        __syncthreads();
        for (int task = wid0; task < 544; task += NW){
            if (task >= 512){
                int r = task - 512;
                dotrow16(Wout + (size_t)r*HH, hs4, bout[r],
                         out + (size_t)(TT-1)*VV + r, TT*VV, lane);
            }
        }
    }

    if (bx == 0 && tid == 0) g_epoch = ep;   // persist epoch base for next launch
}

// ---------------- launch ----------------
extern "C" void kernel_launch(void* const* d_in, const int* in_sizes, int n_in,
                              void* d_out, int out_size){
    const float* enc   = (const float*)d_in[0];
    const float* h0in  = (const float*)d_in[1];
    const float* c0in  = (const float*)d_in[2];
    // d_in[3] = audio_lengths (unused by the reference math)
    const float* Wq    = (const float*)d_in[4];
    const float* bq    = (const float*)d_in[5];
    const float* Wk    = (const float*)d_in[6];
    const float* bk    = (const float*)d_in[7];
    const float* v     = (const float*)d_in[8];
    // d_in[9] = vb (shift-invariant under softmax; omitted)
    const float* Wih0  = (const float*)d_in[10];
    const float* bih0  = (const float*)d_in[11];
    const float* Whh0  = (const float*)d_in[12];
    const float* bhh0  = (const float*)d_in[13];
    const float* Wih1  = (const float*)d_in[14];
    const float* bih1  = (const float*)d_in[15];
    const float* Whh1  = (const float*)d_in[16];
    const float* bhh1  = (const float*)d_in[17];
    const float* Wout  = (const float*)d_in[18];
    const float* bout  = (const float*)d_in[19];
    float* out = (float*)d_out;

    const int SMEM = (NBATCH*1024 + NBATCH*512) * 4;   // 98304 bytes (phase D peak)
    cudaFuncSetAttribute(decoder_persistent, cudaFuncAttributeMaxDynamicSharedMemorySize, SMEM);

    // grid = exactly the number of co-resident blocks (deadlock-proof)
    int dev = 0; cudaGetDevice(&dev);
    int nsm = 0; cudaDeviceGetAttribute(&nsm, cudaDevAttrMultiProcessorCount, dev);
    int maxb = 0;
    cudaOccupancyMaxActiveBlocksPerMultiprocessor(&maxb, decoder_persistent, THREADS, SMEM);
    if (maxb < 1) maxb = 1;
    int grid = nsm * maxb;
    if (grid < 1) grid = 1;
    if (grid > 512) grid = 512;

    decoder_persistent<<<grid, THREADS, SMEM>>>(enc, h0in, c0in, Wq, bq, Wk, bk, v,
                                                Wih0, bih0, Whh0, bhh0,
                                                Wih1, bih1, Whh1, bhh1,
                                                Wout, bout, out);
}